// round 14
// baseline (speedup 1.0000x reference)
#include <cuda_runtime.h>
#include <cuda_fp16.h>
#include <math.h>
#include <stdint.h>

// ---------------- problem constants ----------------
#define BATCH   128
#define CHAN    3
#define HW      224
#define PATCH   16
#define NPD     14
#define NPATCH  (NPD*NPD)           // 196
#define M_DIM   (BATCH*NPATCH)      // 25088
#define K_DIM   (CHAN*PATCH*PATCH)  // 768
#define N_DIM   768

#define PI_D 3.141592653589793238462643383279502884

// fp16 scratch: DCT-folded weights [n][k]; im2col'd input [m][k]
__device__ __half g_wt[N_DIM * K_DIM];
__device__ __half g_xh[(long)M_DIM * K_DIM];

// fp16-accumulate MMA: D(f16x2 pair) = A*B + C
__device__ __forceinline__ void mma_f16acc(unsigned* c, const unsigned* a, const unsigned* b) {
    asm volatile(
        "mma.sync.aligned.m16n8k16.row.col.f16.f16.f16.f16 "
        "{%0,%1}, {%2,%3,%4,%5}, {%6,%7}, {%0,%1};"
        : "+r"(c[0]), "+r"(c[1])
        : "r"(a[0]), "r"(a[1]), "r"(a[2]), "r"(a[3]), "r"(b[0]), "r"(b[1]));
}
#define LDSM_X4(r0, r1, r2, r3, addr) \
    asm volatile("ldmatrix.sync.aligned.m8n8.x4.shared.b16 {%0,%1,%2,%3}, [%4];" \
                 : "=r"(r0), "=r"(r1), "=r"(r2), "=r"(r3) : "r"(addr))
#define CP_ASYNC16(saddr, gptr) \
    asm volatile("cp.async.cg.shared.global [%0], [%1], 16;" :: "r"(saddr), "l"(gptr))
#define CP_COMMIT()  asm volatile("cp.async.commit_group;" ::: "memory")
#define CP_WAIT(n)   asm volatile("cp.async.wait_group %0;" :: "n"(n) : "memory")

// ---------------------------------------------------------------------------
// Kernel 0: im2col x (fp32 NCHW) -> g_xh (fp16, [m][k]).  8 floats per thread.
// ---------------------------------------------------------------------------
__global__ void im2col_h_kernel(const float* __restrict__ x) {
    int f = blockIdx.x * blockDim.x + threadIdx.x;      // 8-float chunk index
    const float4* xp = (const float4*)x + (long)f * 2;
    float4 v0 = xp[0], v1 = xp[1];
    int w8 = f % 28; int rest = f / 28;
    int h = rest % HW; rest /= HW;
    int c = rest % CHAN; int b = rest / CHAN;
    int j = (w8 * 8) & 15, pw = (w8 * 8) >> 4;
    int i = h & 15,        ph = h >> 4;
    long m = (long)b * NPATCH + ph * NPD + pw;
    int  k = c * 256 + i * 16 + j;
    __half2 h0 = __floats2half2_rn(v0.x, v0.y);
    __half2 h1 = __floats2half2_rn(v0.z, v0.w);
    __half2 h2 = __floats2half2_rn(v1.x, v1.y);
    __half2 h3 = __floats2half2_rn(v1.z, v1.w);
    uint4 o;
    o.x = *(unsigned*)&h0; o.y = *(unsigned*)&h1;
    o.z = *(unsigned*)&h2; o.w = *(unsigned*)&h3;
    *(uint4*)(g_xh + m * K_DIM + k) = o;    // 16B aligned: j in {0,8}
}

// ---------------------------------------------------------------------------
// Kernel 1: fold per-8x8 DCT into conv weights (w' = D^T W D), fp16, [n][k].
// ---------------------------------------------------------------------------
__global__ void dct_weight_kernel(const float* __restrict__ w) {
    __shared__ float Ws[16][16];
    __shared__ float Ds[8][8];
    int o = blockIdx.x / CHAN, c = blockIdx.x % CHAN, tid = threadIdx.x;
    if (tid < 64) {
        int k = tid >> 3, n = tid & 7;
        double v = sqrt(2.0 / 8.0) * cos(PI_D * (2.0 * n + 1.0) * k / 16.0);
        if (k == 0) v *= (1.0 / sqrt(2.0));
        Ds[k][n] = (float)v;
    }
    Ws[tid >> 4][tid & 15] = w[(o * CHAN + c) * 256 + tid];
    __syncthreads();
    int i = tid >> 4, j = tid & 15;
    int bi = i & 8, bj = j & 8, ii = i & 7, jj = j & 7;
    float s = 0.0f;
    #pragma unroll
    for (int u = 0; u < 8; u++) {
        float du = Ds[u][ii];
        #pragma unroll
        for (int v = 0; v < 8; v++) s += du * Ws[bi + u][bj + v] * Ds[v][jj];
    }
    g_wt[(long)o * K_DIM + c * 256 + i * 16 + j] = __float2half_rn(s);
}

// ---------------------------------------------------------------------------
// Kernel 2: fp16 mma.sync m16n8k16 GEMM, fp16 ACCUMULATORS (2 sets: even/odd
// k-step), promoted to fp32 in the epilogue.
//   BM=128 BN=128 BK=32, 4-stage cp.async, 2 CTAs/SM, 8 warps (4m x 2n),
//   warp tile 32x64.  K-major fp16 smem, 80B row stride (conflict-free).
// ---------------------------------------------------------------------------
#define BM 128
#define BN 128
#define BK 32
#define STAGES 4
#define NT (K_DIM / BK)          // 24
#define ROWB 80                  // bytes per smem row (64 data + 16 pad)
#define TILE_B (BM * ROWB)       // 10240 bytes per operand tile
#define STG_B (2 * TILE_B)       // A then B : 20480
#define SMEM_BYTES (STAGES * STG_B)   // 81920

__global__ __launch_bounds__(256, 2)
void gemm_f16_kernel(const float* __restrict__ bias, float* __restrict__ out) {
    extern __shared__ __half smem[];
    const unsigned smem_b = (unsigned)__cvta_generic_to_shared(smem);
    const int tid  = threadIdx.x;
    const int lane = tid & 31, wid = tid >> 5;
    const int warp_m = wid >> 1, warp_n = wid & 1;
    const int g = lane >> 2, tig = lane & 3;

    const int m0 = blockIdx.y * BM;
    const int n0 = blockIdx.x * BN;

    // ---- global-load mapping: per operand 512 16B chunks, 2 per thread ----
    const int row0 = tid >> 2;      // rows row0, row0+64
    const int q    = tid & 3;       // 16B chunk within 64B k-row

    const __half* gA0 = g_xh + (long)(m0 + row0) * K_DIM + q * 8;
    const __half* gA1 = g_xh + (long)(m0 + row0 + 64) * K_DIM + q * 8;
    const __half* gB0 = g_wt + (long)(n0 + row0) * K_DIM + q * 8;
    const __half* gB1 = g_wt + (long)(n0 + row0 + 64) * K_DIM + q * 8;

    const unsigned stA0 = row0 * ROWB + q * 16;
    const unsigned stA1 = (row0 + 64) * ROWB + q * 16;

    auto load_tile = [&](int t, int slot) {
        const unsigned base = smem_b + slot * STG_B;
        const int k0 = t * BK;
        CP_ASYNC16(base + stA0, gA0 + k0);
        CP_ASYNC16(base + stA1, gA1 + k0);
        CP_ASYNC16(base + TILE_B + stA0, gB0 + k0);
        CP_ASYNC16(base + TILE_B + stA1, gB1 + k0);
    };

    // ---- ldmatrix per-thread address offsets (within a stage) ----
    const int lm_row = lane & 7;
    const int lm_hi  = (lane >> 3) & 1;    // +8 m rows for mats 1,3
    const int lm_k8  = (lane >> 4) * 8;    // +8 k cols for mats 2,3
    unsigned a_off[2];                     // per mt
    #pragma unroll
    for (int mt = 0; mt < 2; mt++)
        a_off[mt] = (warp_m * 32 + mt * 16 + lm_hi * 8 + lm_row) * ROWB + lm_k8 * 2;
    const int b_hi = (lane >> 3) & 1;      // +8 k cols for mats 1,3
    const int b_nt = (lane >> 4);          // second n-tile for mats 2,3
    unsigned b_off[4];                     // per g2
    #pragma unroll
    for (int g2 = 0; g2 < 4; g2++)
        b_off[g2] = TILE_B + (warp_n * 64 + (2 * g2 + b_nt) * 8 + lm_row) * ROWB
                  + b_hi * 16;

    // fp16 accumulators: even k-steps and odd k-steps, summed at epilogue
    unsigned accE[2][8][2], accO[2][8][2];
    #pragma unroll
    for (int i = 0; i < 2; i++)
        #pragma unroll
        for (int j = 0; j < 8; j++) {
            accE[i][j][0] = 0u; accE[i][j][1] = 0u;
            accO[i][j][0] = 0u; accO[i][j][1] = 0u;
        }

    #pragma unroll
    for (int s = 0; s < STAGES - 1; s++) { load_tile(s, s); CP_COMMIT(); }

    auto compute_tile = [&](unsigned base) {
        unsigned a0[2][4], a1[2][4], b0f[8][2], b1f[8][2];
        #pragma unroll
        for (int mt = 0; mt < 2; mt++)
            LDSM_X4(a0[mt][0], a0[mt][1], a0[mt][2], a0[mt][3], base + a_off[mt]);
        #pragma unroll
        for (int g2 = 0; g2 < 4; g2++)
            LDSM_X4(b0f[2 * g2][0], b0f[2 * g2][1],
                    b0f[2 * g2 + 1][0], b0f[2 * g2 + 1][1], base + b_off[g2]);
        #pragma unroll
        for (int mt = 0; mt < 2; mt++)
            LDSM_X4(a1[mt][0], a1[mt][1], a1[mt][2], a1[mt][3],
                    base + a_off[mt] + 32);
        #pragma unroll
        for (int mt = 0; mt < 2; mt++)
            #pragma unroll
            for (int nt = 0; nt < 8; nt++)
                mma_f16acc(accE[mt][nt], a0[mt], b0f[nt]);
        #pragma unroll
        for (int g2 = 0; g2 < 4; g2++)
            LDSM_X4(b1f[2 * g2][0], b1f[2 * g2][1],
                    b1f[2 * g2 + 1][0], b1f[2 * g2 + 1][1],
                    base + b_off[g2] + 32);
        #pragma unroll
        for (int mt = 0; mt < 2; mt++)
            #pragma unroll
            for (int nt = 0; nt < 8; nt++)
                mma_f16acc(accO[mt][nt], a1[mt], b1f[nt]);
    };

    // main loop: single __syncthreads per tile (slot reuse proven safe in R11)
    for (int t0 = 0; t0 < NT; t0 += STAGES) {
        #pragma unroll
        for (int u = 0; u < STAGES; u++) {
            const int t = t0 + u;
            CP_WAIT(STAGES - 2);
            __syncthreads();
            const int tn = t + STAGES - 1;
            if (tn < NT) load_tile(tn, tn & (STAGES - 1));
            CP_COMMIT();
            compute_tile(smem_b + u * STG_B);
        }
    }

    // ---- epilogue: promote fp16 partials to fp32, add bias, store ----
    #pragma unroll
    for (int mt = 0; mt < 2; mt++) {
        const int r0 = m0 + warp_m * 32 + mt * 16 + g;
        #pragma unroll
        for (int nt = 0; nt < 8; nt++) {
            const int col = n0 + warp_n * 64 + nt * 8 + 2 * tig;
            const float b0 = bias[col], b1 = bias[col + 1];
            float2 e0 = __half22float2(*(__half2*)&accE[mt][nt][0]);
            float2 e1 = __half22float2(*(__half2*)&accE[mt][nt][1]);
            float2 o0 = __half22float2(*(__half2*)&accO[mt][nt][0]);
            float2 o1 = __half22float2(*(__half2*)&accO[mt][nt][1]);
            float2 v0 = make_float2(e0.x + o0.x + b0, e0.y + o0.y + b1);
            float2 v1 = make_float2(e1.x + o1.x + b0, e1.y + o1.y + b1);
            *(float2*)(out + (long)r0 * N_DIM + col)       = v0;
            *(float2*)(out + (long)(r0 + 8) * N_DIM + col) = v1;
        }
    }
}

// ---------------------------------------------------------------------------
extern "C" void kernel_launch(void* const* d_in, const int* in_sizes, int n_in,
                              void* d_out, int out_size) {
    const float* x = (const float*)d_in[0];   // [128,3,224,224]
    const float* w = (const float*)d_in[1];   // [768,3,16,16]
    const float* b = (const float*)d_in[2];   // [768]
    float* out = (float*)d_out;               // [128,196,768]

    cudaFuncSetAttribute(gemm_f16_kernel,
                         cudaFuncAttributeMaxDynamicSharedMemorySize, SMEM_BYTES);

    const int NF8 = BATCH * CHAN * HW * HW / 8;   // 2,408,448
    im2col_h_kernel<<<NF8 / 256, 256>>>(x);
    dct_weight_kernel<<<N_DIM * CHAN, 256>>>(w);
    gemm_f16_kernel<<<dim3(N_DIM / BN, M_DIM / BM), 256, SMEM_BYTES>>>(b, out);
}